// round 2
// baseline (speedup 1.0000x reference)
#include <cuda_runtime.h>
#include <math_constants.h>

// KNN min-dist, 9x9 window, C=3, zero-padded. Packed f32x2 math across dj.
// Fixed shapes: B=4, C=3, H=256, W=512.

#define BDIM 128
#define TW 32
#define TH 16
#define TY 4
#define HALO 4

#define B_ 4
#define H_ 256
#define W_ 512
#define HW_ (H_*W_)

#define SH_H (TH + 2*HALO)   // 24 rows
#define NCOLS 41             // cols 0..40 (dj 0..8 + the dj=9 hi-half partner)
#define CPYB 48              // word offset of shifted copy (48 mod 32 = 16 -> banks disjoint)
#define ROWW 96              // words per row block (copyA @0, copyB @48)

typedef unsigned long long u64;

__device__ __forceinline__ u64 pk2(float lo, float hi){
    u64 r; asm("mov.b64 %0, {%1,%2};" : "=l"(r) : "f"(lo), "f"(hi)); return r;
}
__device__ __forceinline__ void upk2(u64 v, float& lo, float& hi){
    asm("mov.b64 {%0,%1}, %2;" : "=f"(lo), "=f"(hi) : "l"(v));
}
__device__ __forceinline__ u64 add2(u64 a, u64 b){
    u64 r; asm("add.rn.f32x2 %0, %1, %2;" : "=l"(r) : "l"(a), "l"(b)); return r;
}
__device__ __forceinline__ u64 mul2(u64 a, u64 b){
    u64 r; asm("mul.rn.f32x2 %0, %1, %2;" : "=l"(r) : "l"(a), "l"(b)); return r;
}
__device__ __forceinline__ u64 fma2(u64 a, u64 b, u64 c){
    u64 r; asm("fma.rn.f32x2 %0, %1, %2, %3;" : "=l"(r) : "l"(a), "l"(b), "l"(c)); return r;
}

__global__ __launch_bounds__(BDIM) void knn_min_kernel(
    const float* __restrict__ tfm, const float* __restrict__ obs,
    float* __restrict__ out)
{
    __shared__ float s[3][SH_H][ROWW];

    const int b  = blockIdx.z;
    const int x0 = blockIdx.x * TW;
    const int y0 = blockIdx.y * TH;
    const int tid = threadIdx.x;
    const int tx = tid & 31;
    const int ty = tid >> 5;

    const float* obs_b = obs + b * 3 * HW_;
    const float* tfm_b = tfm + b * 3 * HW_;

    // ---- load obs tile: two copies per row (copyB shifted one column left) ----
    for (int idx = tid; idx < 3 * SH_H * NCOLS; idx += BDIM) {
        int c   = idx / (SH_H * NCOLS);
        int rem = idx - c * (SH_H * NCOLS);
        int r   = rem / NCOLS;
        int i   = rem - r * NCOLS;
        int gy = y0 - HALO + r;
        int gx = x0 - HALO + i;
        float v = 0.f;
        if (gy >= 0 && gy < H_ && gx >= 0 && gx < W_)
            v = obs_b[c * HW_ + gy * W_ + gx];
        s[c][r][i] = v;                       // copyA[i]  = row[i]
        if (i >= 1) s[c][r][CPYB + i - 1] = v; // copyB[i-1]= row[i]
    }
    __syncthreads();

    // ---- tfm pixels: negated packed broadcast (-t, -t) per channel/pixel ----
    const int ybase = y0 + ty * TY;
    const int xg = x0 + tx;
    u64 nt[3][TY];
#pragma unroll
    for (int k = 0; k < TY; k++) {
        int g = (ybase + k) * W_ + xg;
#pragma unroll
        for (int c = 0; c < 3; c++) {
            float v = tfm_b[c * HW_ + g];
            nt[c][k] = pk2(-v, -v);
        }
    }

    float mlo[TY], mhi[TY];
#pragma unroll
    for (int k = 0; k < TY; k++) { mlo[k] = CUDART_INF_F; mhi[k] = CUDART_INF_F; }

    // column base: even threads read copyA at tx, odd threads copyB at tx-1
    const int sel = (tx & 1) ? (CPYB + tx - 1) : tx;
    const int rbase = ty * TY;

    // 5 packed dj-pairs: (0,1)(2,3)(4,5)(6,7)(8,9); dj=9 hi-half excluded.
#pragma unroll 1
    for (int j = 0; j < 5; j++) {
        const int col = sel + 2 * j;
        const bool full = (j < 4);
#pragma unroll
        for (int r = 0; r < TY + 8; r++) {
            const float2 o0 = *(const float2*)&s[0][rbase + r][col];
            const float2 o1 = *(const float2*)&s[1][rbase + r][col];
            const float2 o2 = *(const float2*)&s[2][rbase + r][col];
            const u64 p0 = pk2(o0.x, o0.y);
            const u64 p1 = pk2(o1.x, o1.y);
            const u64 p2 = pk2(o2.x, o2.y);
#pragma unroll
            for (int k = 0; k < TY; k++) {
                const int di = r - k;
                if (di >= 0 && di < 9) {
                    u64 d0 = add2(nt[0][k], p0);
                    u64 d1 = add2(nt[1][k], p1);
                    u64 d2 = add2(nt[2][k], p2);
                    u64 a  = mul2(d0, d0);
                    a = fma2(d1, d1, a);
                    a = fma2(d2, d2, a);
                    float alo, ahi;
                    upk2(a, alo, ahi);
                    mlo[k] = fminf(mlo[k], alo);
                    if (full) mhi[k] = fminf(mhi[k], ahi);
                }
            }
        }
    }

    float* out_b = out + b * HW_;
#pragma unroll
    for (int k = 0; k < TY; k++) {
        out_b[(ybase + k) * W_ + xg] = sqrtf(fminf(mlo[k], mhi[k]));
    }
}

extern "C" void kernel_launch(void* const* d_in, const int* in_sizes, int n_in,
                              void* d_out, int out_size)
{
    const float* tfm = (const float*)d_in[0];
    const float* obs = (const float*)d_in[1];
    float* out = (float*)d_out;
    (void)in_sizes; (void)n_in; (void)out_size;

    dim3 grid(W_ / TW, H_ / TH, B_);
    dim3 block(BDIM);
    knn_min_kernel<<<grid, block>>>(tfm, obs, out);
}

// round 3
// speedup vs baseline: 1.3830x; 1.3830x over previous
#include <cuda_runtime.h>
#include <math_constants.h>

// KNN min-dist, 9x9 window, C=3, zero-padded.
// Dot-product expansion: d^2 = |t|^2 + (|o|^2 - 2 t.o); q=|o|^2 precomputed
// into the 4th lane of a float4 smem tile -> 3 FFMA + 1 FMNMX per shift.
// Fixed shapes: B=4, C=3, H=256, W=512.

#define BDIM 128
#define TW 32
#define TH 16
#define TY 4
#define HALO 4
#define SW 9

#define B_ 4
#define H_ 256
#define W_ 512
#define HW_ (H_*W_)

#define SH_H (TH + 2*HALO)   // 24
#define SH_W (TW + 2*HALO)   // 40

__global__ __launch_bounds__(BDIM) void knn_min_kernel(
    const float* __restrict__ tfm, const float* __restrict__ obs,
    float* __restrict__ out)
{
    __shared__ float4 s4[SH_H][SH_W];   // (o0, o1, o2, |o|^2)

    const int b  = blockIdx.z;
    const int x0 = blockIdx.x * TW;
    const int y0 = blockIdx.y * TH;
    const int tid = threadIdx.x;
    const int tx = tid & 31;
    const int ty = tid >> 5;

    const float* obs_b = obs + b * 3 * HW_;
    const float* tfm_b = tfm + b * 3 * HW_;

    // ---- load obs tile (zero-padded halo), compute q = |o|^2 on the fly ----
    for (int idx = tid; idx < SH_H * SH_W; idx += BDIM) {
        int iy = idx / SH_W;
        int ix = idx - iy * SH_W;
        int gy = y0 - HALO + iy;
        int gx = x0 - HALO + ix;
        float v0 = 0.f, v1 = 0.f, v2 = 0.f;
        if (gy >= 0 && gy < H_ && gx >= 0 && gx < W_) {
            int g = gy * W_ + gx;
            v0 = obs_b[g];
            v1 = obs_b[HW_ + g];
            v2 = obs_b[2 * HW_ + g];
        }
        float q = fmaf(v2, v2, fmaf(v1, v1, v0 * v0));
        s4[iy][ix] = make_float4(v0, v1, v2, q);
    }
    __syncthreads();

    // ---- per-pixel constants: nt_c = -2 t_c, tt = |t|^2 ----
    const int ybase = y0 + ty * TY;
    const int xg = x0 + tx;
    float nt0[TY], nt1[TY], nt2[TY], tt[TY], m[TY];
#pragma unroll
    for (int k = 0; k < TY; k++) {
        int g = (ybase + k) * W_ + xg;
        float a = tfm_b[g];
        float c = tfm_b[HW_ + g];
        float e = tfm_b[2 * HW_ + g];
        nt0[k] = -2.f * a;
        nt1[k] = -2.f * c;
        nt2[k] = -2.f * e;
        tt[k]  = fmaf(e, e, fmaf(c, c, a * a));
        m[k] = CUDART_INF_F;
    }

    const int rbase = ty * TY;

#pragma unroll 1
    for (int dj = 0; dj < SW; dj++) {
#pragma unroll
        for (int r = 0; r < TY + 8; r++) {
            const float4 v = s4[rbase + r][tx + dj];
#pragma unroll
            for (int k = 0; k < TY; k++) {
                const int di = r - k;
                if (di >= 0 && di < SW) {
                    float e = fmaf(nt0[k], v.x,
                              fmaf(nt1[k], v.y,
                              fmaf(nt2[k], v.z, v.w)));
                    m[k] = fminf(m[k], e);
                }
            }
        }
    }

    float* out_b = out + b * HW_;
#pragma unroll
    for (int k = 0; k < TY; k++) {
        out_b[(ybase + k) * W_ + xg] = sqrtf(fmaxf(tt[k] + m[k], 0.f));
    }
}

extern "C" void kernel_launch(void* const* d_in, const int* in_sizes, int n_in,
                              void* d_out, int out_size)
{
    const float* tfm = (const float*)d_in[0];
    const float* obs = (const float*)d_in[1];
    float* out = (float*)d_out;
    (void)in_sizes; (void)n_in; (void)out_size;

    dim3 grid(W_ / TW, H_ / TH, B_);
    dim3 block(BDIM);
    knn_min_kernel<<<grid, block>>>(tfm, obs, out);
}